// round 10
// baseline (speedup 1.0000x reference)
#include <cuda_runtime.h>
#include <cuda_bf16.h>

#define NN    50000
#define DIN   128
#define HH    64
#define CC    2
#define EMAX  800000
#define G2    444                      // 148 SMs x 3 CTAs — all co-resident
#define PB    222                      // preprocess blocks
#define GEMMB (G2 - PB)                // gemm blocks
#define NTILES ((NN + 127) / 128)      // 391
#define CHP   ((NN + PB - 1) / PB)     // 226 nodes per preprocess block

// ---------------- scratch (static __device__, no allocation) ----------------
__device__ int d_flag64;
__device__ __align__(16) int   d_cnt[NN];
__device__ __align__(16) int   d_rp [NN + 1];
__device__ __align__(16) int   d_cur[NN];
__device__ __align__(16) int   d_bsum[PB];
__device__ __align__(16) int   d_boff[PB];
__device__ __align__(16) int   d_col[EMAX];
__device__ __align__(16) float d_dinv[NN];
__device__ __align__(16) float d_g1[(size_t)NN * HH];   // raw x@W1 (unscaled)
__device__ __align__(16) float d_g2[NN * CC];           // layer-2 msgs (pre-scaled)

// software grid barriers (monotonic generation -> graph-replay-safe)
__device__ unsigned g_cnt[4];
__device__ unsigned g_gen[4];

__device__ __forceinline__ void gbar(int id, unsigned n) {
    __syncthreads();
    if (threadIdx.x == 0) {
        __threadfence();
        unsigned gen = *(volatile unsigned*)&g_gen[id];
        unsigned arr = atomicAdd(&g_cnt[id], 1u);
        if (arr == n - 1) {
            g_cnt[id] = 0;
            __threadfence();
            atomicAdd(&g_gen[id], 1u);
        } else {
            while (*(volatile unsigned*)&g_gen[id] == gen) { }
        }
        __threadfence();
    }
    __syncthreads();
}

__device__ __forceinline__ int edge_at(const void* p, long long i) {
    if (d_flag64) return (int)((const long long*)p)[i];
    return ((const int*)p)[i];
}

// ---------------- the whole GCN in one persistent kernel --------------------
__global__ void __launch_bounds__(256, 3) k_fused(
    const float* __restrict__ x, const void* __restrict__ ei, int E,
    const float* __restrict__ W1, const float* __restrict__ b1,
    const float* __restrict__ W2, const float* __restrict__ b2,
    float* __restrict__ out)
{
    __shared__ __align__(16) float smf[12288];   // 48 KB, phase-aliased
    const int tid = threadIdx.x;
    const int b   = blockIdx.x;

    if (b < PB) {
        // ================= preprocess group =================
        int* sm = (int*)smf;
        // A: zero counts; block 0 probes int64 vs int32
        for (int i = b * 256 + tid; i < NN; i += PB * 256) d_cnt[i] = 0;
        if (b == 0) {
            const int* p = (const int*)ei;
            if (tid == 0) sm[0] = 1;
            __syncthreads();
            int bad = 0;
            for (int s = tid; s < 1024; s += 256) {
                int lo = p[2 * s], hi = p[2 * s + 1];
                if (hi != 0 || lo < 0 || lo >= NN) bad = 1;
            }
            if (bad) atomicAnd(&sm[0], 0);
            __syncthreads();
            if (tid == 0) d_flag64 = sm[0];
        }
        gbar(0, PB);

        // B: count in-degree (dst half)
        for (int i = b * 256 + tid; i < E; i += PB * 256) {
            int d = edge_at(ei, (long long)E + i);
            atomicAdd(&d_cnt[d], 1);
        }
        gbar(0, PB);

        // C1: per-block pairwise scan of chunk [b*CHP, b*CHP+CHP)
        {
            const int base = b * CHP;
            const int end  = min(base + CHP, NN);
            const int t0   = base + tid * 2;
            int c0 = (t0     < end) ? d_cnt[t0]     : 0;
            int c1 = (t0 + 1 < end) ? d_cnt[t0 + 1] : 0;
            int v = c0 + c1;
            sm[tid] = v;
            __syncthreads();
            #pragma unroll
            for (int off = 1; off < 256; off <<= 1) {
                int t = (tid >= off) ? sm[tid - off] : 0;
                __syncthreads();
                sm[tid] += t;
                __syncthreads();
            }
            int excl = sm[tid] - v;
            if (t0     < end) d_rp[t0]     = excl;
            if (t0 + 1 < end) d_rp[t0 + 1] = excl + c0;
            if (tid == 255) d_bsum[b] = sm[255];
        }
        gbar(0, PB);

        // C2: block 0 scans the PB block sums (pairwise)
        if (b == 0) {
            const int t0 = tid * 2;
            int v0 = (t0     < PB) ? d_bsum[t0]     : 0;
            int v1 = (t0 + 1 < PB) ? d_bsum[t0 + 1] : 0;
            int v = v0 + v1;
            sm[tid] = v;
            __syncthreads();
            #pragma unroll
            for (int off = 1; off < 256; off <<= 1) {
                int t = (tid >= off) ? sm[tid - off] : 0;
                __syncthreads();
                sm[tid] += t;
                __syncthreads();
            }
            int excl = sm[tid] - v;
            if (t0     < PB) d_boff[t0]     = excl;
            if (t0 + 1 < PB) d_boff[t0 + 1] = excl + v0;
            if (tid == 255) d_rp[NN] = sm[255];
        }
        gbar(0, PB);

        // C3: add block offset; init cursor; dinv = rsqrt(1+deg)
        {
            const int base = b * CHP;
            const int end  = min(base + CHP, NN);
            const int off  = d_boff[b];
            for (int i = base + tid; i < end; i += 256) {
                int r = d_rp[i] + off;
                d_rp[i]  = r;
                d_cur[i] = r;
                d_dinv[i] = rsqrtf((float)(1 + d_cnt[i]));
            }
        }
        gbar(0, PB);

        // D: bucket edges into CSR
        for (int e = b * 256 + tid; e < E; e += PB * 256) {
            int s = edge_at(ei, e);
            int d = edge_at(ei, (long long)E + e);
            int pos = atomicAdd(&d_cur[d], 1);
            d_col[pos] = s;
        }
    } else {
        // ================= gemm group: g1 = x @ W1 (raw) =================
        float (*xs)[64] = (float(*)[64])smf;           // 32 KB
        float (*Ws)[64] = (float(*)[64])(smf + 8192);  // 16 KB
        const int tx = tid & 15;
        const int ty = tid >> 4;

        for (int t = b - PB; t < NTILES; t += GEMMB) {
            const int nb = t * 128;
            float acc[8][4];
            #pragma unroll
            for (int j = 0; j < 8; j++)
                #pragma unroll
                for (int c = 0; c < 4; c++) acc[j][c] = 0.0f;

            for (int kk = 0; kk < DIN; kk += 64) {
                __syncthreads();
                for (int i = tid; i < 1024; i += 256) {
                    int r = i >> 4, c4 = i & 15;
                    ((float4*)Ws[r])[c4] =
                        ((const float4*)(W1 + (size_t)(kk + r) * HH))[c4];
                }
                for (int i = tid; i < 2048; i += 256) {
                    int r = i >> 4, c4 = i & 15;
                    int node = nb + r;
                    float4 v = make_float4(0.f, 0.f, 0.f, 0.f);
                    if (node < NN)
                        v = ((const float4*)(x + (size_t)node * DIN + kk))[c4];
                    ((float4*)xs[r])[c4] = v;
                }
                __syncthreads();

                #pragma unroll 8
                for (int k = 0; k < 64; k++) {
                    float4 w = ((float4*)Ws[k])[tx];
                    #pragma unroll
                    for (int j = 0; j < 8; j++) {
                        float xv = xs[ty * 8 + j][k];
                        acc[j][0] = fmaf(xv, w.x, acc[j][0]);
                        acc[j][1] = fmaf(xv, w.y, acc[j][1]);
                        acc[j][2] = fmaf(xv, w.z, acc[j][2]);
                        acc[j][3] = fmaf(xv, w.w, acc[j][3]);
                    }
                }
            }

            #pragma unroll
            for (int j = 0; j < 8; j++) {
                int node = nb + ty * 8 + j;
                if (node < NN) {
                    float4 v = make_float4(acc[j][0], acc[j][1],
                                           acc[j][2], acc[j][3]);
                    ((float4*)(d_g1 + (size_t)node * HH))[tx] = v;
                }
            }
        }
    }

    gbar(2, G2);   // join: CSR + dinv + g1 all ready

    // ======= agg1: gather + dinv[src] scale + relu/bias + GEMM2, warp/node ==
    {
        float* w2s = smf;         // 128 floats
        float* b1s = smf + 128;   // 64 floats
        if (tid < HH * CC)              w2s[tid]       = W2[tid];
        else if (tid < HH * CC + HH)    b1s[tid - 128] = b1[tid - 128];
        __syncthreads();

        const int warp = tid >> 5, lane = tid & 31;
        const float2* __restrict__ g1v = (const float2*)d_g1;

        for (int node = b * 8 + warp; node < NN; node += G2 * 8) {
            const float di = d_dinv[node];
            float2 h = g1v[(size_t)node * 32 + lane];
            float2 acc = make_float2(di * h.x, di * h.y);   // self-loop

            const int rs = d_rp[node], re = d_rp[node + 1];
            int k = rs;
            for (; k + 3 < re; k += 4) {
                int s0 = d_col[k], s1 = d_col[k+1], s2 = d_col[k+2], s3 = d_col[k+3];
                float w0 = d_dinv[s0], w1 = d_dinv[s1],
                      wv2 = d_dinv[s2], w3 = d_dinv[s3];
                float2 v0 = g1v[(size_t)s0 * 32 + lane];
                float2 v1 = g1v[(size_t)s1 * 32 + lane];
                float2 v2 = g1v[(size_t)s2 * 32 + lane];
                float2 v3 = g1v[(size_t)s3 * 32 + lane];
                acc.x = fmaf(w0, v0.x, fmaf(w1, v1.x, fmaf(wv2, v2.x, fmaf(w3, v3.x, acc.x))));
                acc.y = fmaf(w0, v0.y, fmaf(w1, v1.y, fmaf(wv2, v2.y, fmaf(w3, v3.y, acc.y))));
            }
            for (; k < re; k++) {
                int s = d_col[k];
                float w = d_dinv[s];
                float2 v = g1v[(size_t)s * 32 + lane];
                acc.x = fmaf(w, v.x, acc.x);
                acc.y = fmaf(w, v.y, acc.y);
            }

            float h0 = fmaxf(fmaf(di, acc.x, b1s[2 * lane    ]), 0.0f);
            float h1 = fmaxf(fmaf(di, acc.y, b1s[2 * lane + 1]), 0.0f);
            float a0 = h0 * w2s[4 * lane + 0] + h1 * w2s[4 * lane + 2];
            float a1 = h0 * w2s[4 * lane + 1] + h1 * w2s[4 * lane + 3];
            #pragma unroll
            for (int off = 16; off; off >>= 1) {
                a0 += __shfl_xor_sync(0xffffffff, a0, off);
                a1 += __shfl_xor_sync(0xffffffff, a1, off);
            }
            if (lane == 0)
                *(float2*)(d_g2 + node * CC) = make_float2(a0 * di, a1 * di);
        }
    }

    gbar(3, G2);

    // ======= agg2: 4 lanes per node, quad shfl reduce =======
    {
        const int sub  = tid & 3;
        const int quad = tid >> 2;                  // 0..63 in block
        const float2* __restrict__ g2v = (const float2*)d_g2;

        for (int node = b * 64 + quad; node < NN; node += G2 * 64) {
            float2 acc = make_float2(0.0f, 0.0f);
            const int rs = d_rp[node], re = d_rp[node + 1];
            for (int k = rs + sub; k < re; k += 4) {
                float2 v = g2v[d_col[k]];
                acc.x += v.x; acc.y += v.y;
            }
            acc.x += __shfl_down_sync(0xffffffff, acc.x, 2, 4);
            acc.y += __shfl_down_sync(0xffffffff, acc.y, 2, 4);
            acc.x += __shfl_down_sync(0xffffffff, acc.x, 1, 4);
            acc.y += __shfl_down_sync(0xffffffff, acc.y, 1, 4);
            if (sub == 0) {
                float2 self = g2v[node];
                acc.x += self.x; acc.y += self.y;
                const float di = d_dinv[node];
                *(float2*)(out + node * CC) =
                    make_float2(fmaf(di, acc.x, b2[0]), fmaf(di, acc.y, b2[1]));
            }
        }
    }
}

// ---------------- launch ----------------------------------------------------
extern "C" void kernel_launch(void* const* d_in, const int* in_sizes, int n_in,
                              void* d_out, int out_size) {
    const float* x  = (const float*)d_in[0];
    const void*  ei = d_in[1];
    const float* W1 = (const float*)d_in[2];
    const float* b1 = (const float*)d_in[3];
    const float* W2 = (const float*)d_in[4];
    const float* b2 = (const float*)d_in[5];
    float* out = (float*)d_out;

    const int E = in_sizes[1] / 2;

    k_fused<<<G2, 256>>>(x, ei, E, W1, b1, W2, b2, out);
}

// round 11
// speedup vs baseline: 1.1673x; 1.1673x over previous
#include <cuda_runtime.h>
#include <cuda_bf16.h>
#include <cuda_fp16.h>

#define NN    50000
#define DIN   128
#define HH    64
#define CC    2
#define EMAX  800000
#define NB    ((NN + 255) / 256)   // 196 scan blocks

// ---------------- scratch (static __device__, no allocation) ----------------
__device__ int d_flag64;
__device__ __align__(16) int     d_cnt[NN];
__device__ __align__(16) int     d_rp [NN + 1];
__device__ __align__(16) int     d_cur[NN];
__device__ __align__(16) int     d_bsum[NB];
__device__ __align__(16) int     d_boff[NB];
__device__ __align__(16) int     d_col[EMAX];
__device__ __align__(16) float   d_dinv[NN];
__device__ __align__(16) __half2 d_g1h[(size_t)NN * 32];  // fp16 msgs: (x@W1)*dinv
__device__ __align__(16) float   d_g2[NN * CC];           // layer-2 msgs (fp32)

__device__ __forceinline__ int edge_at(const void* p, long long i) {
    if (d_flag64) return (int)((const long long*)p)[i];
    return ((const int*)p)[i];
}

// ------------- init: zero counts; block 0 also probes int64/int32 -----------
__global__ void k_init(const int* __restrict__ p) {
    int i = blockIdx.x * blockDim.x + threadIdx.x;
    if (i < NN) d_cnt[i] = 0;
    if (blockIdx.x == 0) {
        __shared__ int ok;
        if (threadIdx.x == 0) ok = 1;
        __syncthreads();
        int bad = 0;
        for (int s = threadIdx.x; s < 1024; s += blockDim.x) {
            int lo = p[2 * s], hi = p[2 * s + 1];
            if (hi != 0 || lo < 0 || lo >= NN) bad = 1;
        }
        if (bad) atomicAnd(&ok, 0);
        __syncthreads();
        if (threadIdx.x == 0) d_flag64 = ok;
    }
}

// count in-degree (dst half only)
__global__ void k_count(const void* __restrict__ p, int E) {
    int i = blockIdx.x * blockDim.x + threadIdx.x;
    if (i >= E) return;
    int d = edge_at(p, (long long)E + i);
    atomicAdd(&d_cnt[d], 1);
}

// ---------------- two-level scan --------------------------------------------
__global__ void __launch_bounds__(256) k_scan1() {
    __shared__ int sm[256];
    const int tid = threadIdx.x;
    const int i   = blockIdx.x * 256 + tid;
    int v = (i < NN) ? d_cnt[i] : 0;
    sm[tid] = v;
    __syncthreads();
    #pragma unroll
    for (int off = 1; off < 256; off <<= 1) {
        int t = (tid >= off) ? sm[tid - off] : 0;
        __syncthreads();
        sm[tid] += t;
        __syncthreads();
    }
    if (i < NN) d_rp[i] = sm[tid] - v;          // exclusive, block-local
    if (tid == 255) d_bsum[blockIdx.x] = sm[255];
}

__global__ void __launch_bounds__(256) k_scan2() {
    __shared__ int sm[256];
    const int tid = threadIdx.x;
    int v = (tid < NB) ? d_bsum[tid] : 0;
    sm[tid] = v;
    __syncthreads();
    #pragma unroll
    for (int off = 1; off < 256; off <<= 1) {
        int t = (tid >= off) ? sm[tid - off] : 0;
        __syncthreads();
        sm[tid] += t;
        __syncthreads();
    }
    if (tid < NB) d_boff[tid] = sm[tid] - v;
    if (tid == NB - 1) d_rp[NN] = sm[tid];
}

__global__ void __launch_bounds__(256) k_scan3() {
    const int i = blockIdx.x * 256 + threadIdx.x;
    if (i >= NN) return;
    int r = d_rp[i] + d_boff[blockIdx.x];
    d_rp[i]  = r;
    d_cur[i] = r;
    d_dinv[i] = rsqrtf((float)(1 + d_cnt[i]));
}

// fill CSR col array (order nondeterministic; sum tolerance covers it)
__global__ void k_bucket(const void* __restrict__ p, int E) {
    int e = blockIdx.x * blockDim.x + threadIdx.x;
    if (e >= E) return;
    int s = edge_at(p, e);
    int d = edge_at(p, (long long)E + e);
    int pos = atomicAdd(&d_cur[d], 1);
    d_col[pos] = s;
}

// ---------------- layer 1 GEMM: g1 = (x @ W1) * dinv  -> fp16 ---------------
// tile 128 nodes x 64 outs, 256 threads, 8x4 micro-tile (proven round-4 tiling)
__global__ void __launch_bounds__(256) k_gemm1(const float* __restrict__ x,
                                               const float* __restrict__ W1) {
    __shared__ float xs[128][64];   // 32 KB
    __shared__ float Ws[64][64];    // 16 KB
    const int tid = threadIdx.x;
    const int tx = tid & 15;        // out group: o = 4*tx
    const int ty = tid >> 4;        // node group: n = ty*8 + j
    const int nb = blockIdx.x * 128;

    float acc[8][4];
    #pragma unroll
    for (int j = 0; j < 8; j++)
        #pragma unroll
        for (int c = 0; c < 4; c++) acc[j][c] = 0.0f;

    for (int kk = 0; kk < DIN; kk += 64) {
        __syncthreads();
        for (int i = tid; i < 1024; i += 256) {
            int r = i >> 4, c4 = i & 15;
            ((float4*)Ws[r])[c4] = ((const float4*)(W1 + (size_t)(kk + r) * HH))[c4];
        }
        for (int i = tid; i < 2048; i += 256) {
            int r = i >> 4, c4 = i & 15;
            int node = nb + r;
            float4 v = make_float4(0.f, 0.f, 0.f, 0.f);
            if (node < NN) v = ((const float4*)(x + (size_t)node * DIN + kk))[c4];
            ((float4*)xs[r])[c4] = v;
        }
        __syncthreads();

        #pragma unroll 8
        for (int k = 0; k < 64; k++) {
            float4 w = ((float4*)Ws[k])[tx];
            #pragma unroll
            for (int j = 0; j < 8; j++) {
                float xv = xs[ty * 8 + j][k];
                acc[j][0] = fmaf(xv, w.x, acc[j][0]);
                acc[j][1] = fmaf(xv, w.y, acc[j][1]);
                acc[j][2] = fmaf(xv, w.z, acc[j][2]);
                acc[j][3] = fmaf(xv, w.w, acc[j][3]);
            }
        }
    }

    #pragma unroll
    for (int j = 0; j < 8; j++) {
        int node = nb + ty * 8 + j;
        if (node < NN) {
            float di = d_dinv[node];
            __half2 h0 = __floats2half2_rn(acc[j][0] * di, acc[j][1] * di);
            __half2 h1 = __floats2half2_rn(acc[j][2] * di, acc[j][3] * di);
            d_g1h[(size_t)node * 32 + 2 * tx    ] = h0;
            d_g1h[(size_t)node * 32 + 2 * tx + 1] = h1;
        }
    }
}

// ------- fused: aggregate layer1 (fp16 gather) + relu/bias + GEMM2 ----------
// warp per node: lane holds cols [2*lane, 2*lane+1] as one __half2 (4B/lane)
__global__ void __launch_bounds__(256) k_agg1(const float* __restrict__ b1,
                                              const float* __restrict__ W2) {
    __shared__ float w2s[HH * CC];
    __shared__ float b1s[HH];
    const int tid = threadIdx.x;
    if (tid < HH * CC) w2s[tid] = W2[tid];
    if (tid < HH)      b1s[tid] = b1[tid];
    __syncthreads();

    const int warp = tid >> 5, lane = tid & 31;
    const int node = blockIdx.x * 8 + warp;
    if (node >= NN) return;

    float2 acc = __half22float2(d_g1h[(size_t)node * 32 + lane]);  // self-loop

    const int rs = d_rp[node], re = d_rp[node + 1];
    int k = rs;
    for (; k + 3 < re; k += 4) {
        int s0 = d_col[k], s1 = d_col[k + 1], s2 = d_col[k + 2], s3 = d_col[k + 3];
        __half2 a0 = d_g1h[(size_t)s0 * 32 + lane];
        __half2 a1 = d_g1h[(size_t)s1 * 32 + lane];
        __half2 a2 = d_g1h[(size_t)s2 * 32 + lane];
        __half2 a3 = d_g1h[(size_t)s3 * 32 + lane];
        float2 v0 = __half22float2(a0), v1 = __half22float2(a1);
        float2 v2 = __half22float2(a2), v3 = __half22float2(a3);
        acc.x += (v0.x + v1.x) + (v2.x + v3.x);
        acc.y += (v0.y + v1.y) + (v2.y + v3.y);
    }
    for (; k < re; k++) {
        float2 v = __half22float2(d_g1h[(size_t)d_col[k] * 32 + lane]);
        acc.x += v.x; acc.y += v.y;
    }

    const float di = d_dinv[node];
    float h0 = fmaxf(fmaf(di, acc.x, b1s[2 * lane    ]), 0.0f);
    float h1 = fmaxf(fmaf(di, acc.y, b1s[2 * lane + 1]), 0.0f);
    float a0 = h0 * w2s[4 * lane + 0] + h1 * w2s[4 * lane + 2];
    float a1 = h0 * w2s[4 * lane + 1] + h1 * w2s[4 * lane + 3];
    #pragma unroll
    for (int off = 16; off; off >>= 1) {
        a0 += __shfl_xor_sync(0xffffffff, a0, off);
        a1 += __shfl_xor_sync(0xffffffff, a1, off);
    }
    if (lane == 0)
        *(float2*)(d_g2 + node * CC) = make_float2(a0 * di, a1 * di);
}

// ---------- layer 2 aggregate: 4 lanes per node, quad shfl reduce -----------
__global__ void __launch_bounds__(256) k_agg2(float* __restrict__ out,
                                              const float* __restrict__ b2) {
    const int tid  = threadIdx.x;
    const int sub  = tid & 3;
    const int quad = tid >> 2;                  // 0..63 in block
    const int node = blockIdx.x * 64 + quad;
    if (node >= NN) return;
    const float2* __restrict__ g2v = (const float2*)d_g2;

    float2 acc = make_float2(0.0f, 0.0f);
    const int rs = d_rp[node], re = d_rp[node + 1];
    for (int k = rs + sub; k < re; k += 4) {
        float2 v = g2v[d_col[k]];
        acc.x += v.x; acc.y += v.y;
    }
    acc.x += __shfl_down_sync(0xffffffff, acc.x, 2, 4);
    acc.y += __shfl_down_sync(0xffffffff, acc.y, 2, 4);
    acc.x += __shfl_down_sync(0xffffffff, acc.x, 1, 4);
    acc.y += __shfl_down_sync(0xffffffff, acc.y, 1, 4);
    if (sub == 0) {
        float2 self = g2v[node];
        acc.x += self.x; acc.y += self.y;
        const float di = d_dinv[node];
        *(float2*)(out + node * CC) =
            make_float2(fmaf(di, acc.x, b2[0]), fmaf(di, acc.y, b2[1]));
    }
}

// ---------------- launch ----------------------------------------------------
extern "C" void kernel_launch(void* const* d_in, const int* in_sizes, int n_in,
                              void* d_out, int out_size) {
    const float* x  = (const float*)d_in[0];
    const void*  ei = d_in[1];
    const float* W1 = (const float*)d_in[2];
    const float* b1 = (const float*)d_in[3];
    const float* W2 = (const float*)d_in[4];
    const float* b2 = (const float*)d_in[5];
    float* out = (float*)d_out;

    const int E = in_sizes[1] / 2;

    k_init  <<<NB, 256>>>((const int*)ei);
    k_count <<<(E + 255) / 256, 256>>>(ei, E);
    k_scan1 <<<NB, 256>>>();
    k_scan2 <<<1, 256>>>();
    k_scan3 <<<NB, 256>>>();
    k_bucket<<<(E + 255) / 256, 256>>>(ei, E);
    k_gemm1 <<<(NN + 127) / 128, 256>>>(x, W1);
    k_agg1  <<<(NN + 7) / 8, 256>>>(b1, W2);
    k_agg2  <<<(NN + 63) / 64, 256>>>(out, b2);
}

// round 15
// speedup vs baseline: 1.2412x; 1.0633x over previous
#include <cuda_runtime.h>
#include <cuda_bf16.h>
#include <cuda_fp16.h>

#define NN    50000
#define DIN   128
#define HH    64
#define CC    2
#define EMAX  800000
#define NB    ((NN + 255) / 256)   // 196 scan blocks

// ---------------- scratch (static __device__, no allocation) ----------------
__device__ int d_flag64;
__device__ __align__(16) int     d_cnt[NN];
__device__ __align__(16) int     d_rp [NN + 1];
__device__ __align__(16) int     d_cur[NN];
__device__ __align__(16) int     d_bsum[NB];
__device__ __align__(16) int     d_col[EMAX];
__device__ __align__(16) float   d_dinv[NN];
__device__ __align__(16) __half2 d_g1h[(size_t)NN * 32];  // RAW x@W1 (fp16)
__device__ __align__(16) float   d_g2[NN * CC];           // layer-2 msgs (fp32)

__device__ __forceinline__ int edge_at(const void* p, long long i) {
    if (d_flag64) return (int)((const long long*)p)[i];
    return ((const int*)p)[i];
}

// ------------- init: zero counts; block 0 also probes int64/int32 -----------
__global__ void k_init(const int* __restrict__ p) {
    int i = blockIdx.x * blockDim.x + threadIdx.x;
    if (i < NN) d_cnt[i] = 0;
    if (blockIdx.x == 0) {
        __shared__ int ok;
        if (threadIdx.x == 0) ok = 1;
        __syncthreads();
        int bad = 0;
        for (int s = threadIdx.x; s < 1024; s += blockDim.x) {
            int lo = p[2 * s], hi = p[2 * s + 1];
            if (hi != 0 || lo < 0 || lo >= NN) bad = 1;
        }
        if (bad) atomicAnd(&ok, 0);
        __syncthreads();
        if (threadIdx.x == 0) d_flag64 = ok;
    }
}

// count in-degree (dst half only)
__global__ void k_count(const void* __restrict__ p, int E) {
    int i = blockIdx.x * blockDim.x + threadIdx.x;
    if (i >= E) return;
    int d = edge_at(p, (long long)E + i);
    atomicAdd(&d_cnt[d], 1);
}

// ---------------- scan stage 1: per-block scan + block sums ----------------
__global__ void __launch_bounds__(256) k_scan1() {
    __shared__ int sm[256];
    const int tid = threadIdx.x;
    const int i   = blockIdx.x * 256 + tid;
    int v = (i < NN) ? d_cnt[i] : 0;
    sm[tid] = v;
    __syncthreads();
    #pragma unroll
    for (int off = 1; off < 256; off <<= 1) {
        int t = (tid >= off) ? sm[tid - off] : 0;
        __syncthreads();
        sm[tid] += t;
        __syncthreads();
    }
    if (i < NN) d_rp[i] = sm[tid] - v;          // exclusive, block-local
    if (tid == 255) d_bsum[blockIdx.x] = sm[255];
}

// ---- scan stage 2 (merged): each block warp-sums its prefix of d_bsum ------
__global__ void __launch_bounds__(256) k_scan3() {
    __shared__ int soff;
    const int tid = threadIdx.x;
    const int b   = blockIdx.x;
    if (tid < 32) {
        int s = 0;
        for (int j = tid; j < b; j += 32) s += d_bsum[j];
        #pragma unroll
        for (int off = 16; off; off >>= 1)
            s += __shfl_down_sync(0xffffffff, s, off);
        if (tid == 0) soff = s;
    }
    __syncthreads();
    const int off = soff;
    const int i = b * 256 + tid;
    if (i < NN) {
        int r = d_rp[i] + off;
        d_rp[i]  = r;
        d_cur[i] = r;
        d_dinv[i] = rsqrtf((float)(1 + d_cnt[i]));
    }
    if (b == NB - 1 && tid == 0)
        d_rp[NN] = off + d_bsum[NB - 1];
}

// fill CSR col array (order nondeterministic; sum tolerance covers it)
__global__ void k_bucket(const void* __restrict__ p, int E) {
    int e = blockIdx.x * blockDim.x + threadIdx.x;
    if (e >= E) return;
    int s = edge_at(p, e);
    int d = edge_at(p, (long long)E + e);
    int pos = atomicAdd(&d_cur[d], 1);
    d_col[pos] = s;
}

// ---------------- layer 1 GEMM: g1_raw = x @ W1  -> fp16 (UNSCALED) ---------
// runs concurrently with preprocessing (no dependency on graph/dinv)
__global__ void __launch_bounds__(256) k_gemm1(const float* __restrict__ x,
                                               const float* __restrict__ W1) {
    __shared__ float xs[128][64];   // 32 KB
    __shared__ float Ws[64][64];    // 16 KB
    const int tid = threadIdx.x;
    const int tx = tid & 15;        // out group: o = 4*tx
    const int ty = tid >> 4;        // node group: n = ty*8 + j
    const int nb = blockIdx.x * 128;

    float acc[8][4];
    #pragma unroll
    for (int j = 0; j < 8; j++)
        #pragma unroll
        for (int c = 0; c < 4; c++) acc[j][c] = 0.0f;

    for (int kk = 0; kk < DIN; kk += 64) {
        __syncthreads();
        for (int i = tid; i < 1024; i += 256) {
            int r = i >> 4, c4 = i & 15;
            ((float4*)Ws[r])[c4] = ((const float4*)(W1 + (size_t)(kk + r) * HH))[c4];
        }
        for (int i = tid; i < 2048; i += 256) {
            int r = i >> 4, c4 = i & 15;
            int node = nb + r;
            float4 v = make_float4(0.f, 0.f, 0.f, 0.f);
            if (node < NN) v = ((const float4*)(x + (size_t)node * DIN + kk))[c4];
            ((float4*)xs[r])[c4] = v;
        }
        __syncthreads();

        #pragma unroll 8
        for (int k = 0; k < 64; k++) {
            float4 w = ((float4*)Ws[k])[tx];
            #pragma unroll
            for (int j = 0; j < 8; j++) {
                float xv = xs[ty * 8 + j][k];
                acc[j][0] = fmaf(xv, w.x, acc[j][0]);
                acc[j][1] = fmaf(xv, w.y, acc[j][1]);
                acc[j][2] = fmaf(xv, w.z, acc[j][2]);
                acc[j][3] = fmaf(xv, w.w, acc[j][3]);
            }
        }
    }

    #pragma unroll
    for (int j = 0; j < 8; j++) {
        int node = nb + ty * 8 + j;
        if (node < NN) {
            __half2 h0 = __floats2half2_rn(acc[j][0], acc[j][1]);
            __half2 h1 = __floats2half2_rn(acc[j][2], acc[j][3]);
            d_g1h[(size_t)node * 32 + 2 * tx    ] = h0;
            d_g1h[(size_t)node * 32 + 2 * tx + 1] = h1;
        }
    }
}

// --- fused: aggregate layer1 (fp16 gather, dinv[s] per edge) + GEMM2 --------
// warp per node: lane holds cols [2*lane, 2*lane+1] as one __half2
__global__ void __launch_bounds__(256) k_agg1(const float* __restrict__ b1,
                                              const float* __restrict__ W2) {
    __shared__ float w2s[HH * CC];
    __shared__ float b1s[HH];
    const int tid = threadIdx.x;
    if (tid < HH * CC) w2s[tid] = W2[tid];
    if (tid < HH)      b1s[tid] = b1[tid];
    __syncthreads();

    const int warp = tid >> 5, lane = tid & 31;
    const int node = blockIdx.x * 8 + warp;
    if (node >= NN) return;

    const float di = d_dinv[node];
    float2 self = __half22float2(d_g1h[(size_t)node * 32 + lane]);
    float2 acc = make_float2(di * self.x, di * self.y);   // self-loop

    const int rs = d_rp[node], re = d_rp[node + 1];
    int k = rs;
    for (; k + 3 < re; k += 4) {
        int s0 = d_col[k], s1 = d_col[k + 1], s2 = d_col[k + 2], s3 = d_col[k + 3];
        float w0 = d_dinv[s0], w1 = d_dinv[s1], w2 = d_dinv[s2], w3 = d_dinv[s3];
        float2 v0 = __half22float2(d_g1h[(size_t)s0 * 32 + lane]);
        float2 v1 = __half22float2(d_g1h[(size_t)s1 * 32 + lane]);
        float2 v2 = __half22float2(d_g1h[(size_t)s2 * 32 + lane]);
        float2 v3 = __half22float2(d_g1h[(size_t)s3 * 32 + lane]);
        acc.x = fmaf(w0, v0.x, fmaf(w1, v1.x, fmaf(w2, v2.x, fmaf(w3, v3.x, acc.x))));
        acc.y = fmaf(w0, v0.y, fmaf(w1, v1.y, fmaf(w2, v2.y, fmaf(w3, v3.y, acc.y))));
    }
    for (; k < re; k++) {
        int s = d_col[k];
        float w = d_dinv[s];
        float2 v = __half22float2(d_g1h[(size_t)s * 32 + lane]);
        acc.x = fmaf(w, v.x, acc.x);
        acc.y = fmaf(w, v.y, acc.y);
    }

    float h0 = fmaxf(fmaf(di, acc.x, b1s[2 * lane    ]), 0.0f);
    float h1 = fmaxf(fmaf(di, acc.y, b1s[2 * lane + 1]), 0.0f);
    float a0 = h0 * w2s[4 * lane + 0] + h1 * w2s[4 * lane + 2];
    float a1 = h0 * w2s[4 * lane + 1] + h1 * w2s[4 * lane + 3];
    #pragma unroll
    for (int off = 16; off; off >>= 1) {
        a0 += __shfl_xor_sync(0xffffffff, a0, off);
        a1 += __shfl_xor_sync(0xffffffff, a1, off);
    }
    if (lane == 0)
        *(float2*)(d_g2 + node * CC) = make_float2(a0 * di, a1 * di);
}

// ---------- layer 2 aggregate: 4 lanes per node, quad shfl reduce -----------
__global__ void __launch_bounds__(256) k_agg2(float* __restrict__ out,
                                              const float* __restrict__ b2) {
    const int tid  = threadIdx.x;
    const int sub  = tid & 3;
    const int quad = tid >> 2;                  // 0..63 in block
    const int node = blockIdx.x * 64 + quad;
    if (node >= NN) return;
    const float2* __restrict__ g2v = (const float2*)d_g2;

    float2 acc = make_float2(0.0f, 0.0f);
    const int rs = d_rp[node], re = d_rp[node + 1];
    for (int k = rs + sub; k < re; k += 4) {
        float2 v = g2v[d_col[k]];
        acc.x += v.x; acc.y += v.y;
    }
    acc.x += __shfl_down_sync(0xffffffff, acc.x, 2, 4);
    acc.y += __shfl_down_sync(0xffffffff, acc.y, 2, 4);
    acc.x += __shfl_down_sync(0xffffffff, acc.x, 1, 4);
    acc.y += __shfl_down_sync(0xffffffff, acc.y, 1, 4);
    if (sub == 0) {
        float2 self = g2v[node];
        acc.x += self.x; acc.y += self.y;
        const float di = d_dinv[node];
        *(float2*)(out + node * CC) =
            make_float2(fmaf(di, acc.x, b2[0]), fmaf(di, acc.y, b2[1]));
    }
}

// ---------------- launch: fork gemm1 onto a side stream ---------------------
extern "C" void kernel_launch(void* const* d_in, const int* in_sizes, int n_in,
                              void* d_out, int out_size) {
    const float* x  = (const float*)d_in[0];
    const void*  ei = d_in[1];
    const float* W1 = (const float*)d_in[2];
    const float* b1 = (const float*)d_in[3];
    const float* W2 = (const float*)d_in[4];
    const float* b2 = (const float*)d_in[5];
    float* out = (float*)d_out;

    const int E = in_sizes[1] / 2;

    // created once, on the first (non-captured) correctness call
    static cudaStream_t s2 = nullptr;
    static cudaEvent_t evFork = nullptr, evJoin = nullptr;
    if (!s2) {
        cudaStreamCreateWithFlags(&s2, cudaStreamNonBlocking);
        cudaEventCreateWithFlags(&evFork, cudaEventDisableTiming);
        cudaEventCreateWithFlags(&evJoin, cudaEventDisableTiming);
    }

    // fork: gemm1 (independent of graph preprocessing) on side stream
    cudaEventRecord(evFork, 0);
    cudaStreamWaitEvent(s2, evFork, 0);
    k_gemm1<<<(NN + 127) / 128, 256, 0, s2>>>(x, W1);
    cudaEventRecord(evJoin, s2);

    // preprocessing chain on the main (captured) stream
    k_init  <<<NB, 256>>>((const int*)ei);
    k_count <<<(E + 255) / 256, 256>>>(ei, E);
    k_scan1 <<<NB, 256>>>();
    k_scan3 <<<NB, 256>>>();
    k_bucket<<<(E + 255) / 256, 256>>>(ei, E);

    // join, then aggregation
    cudaStreamWaitEvent(0, evJoin, 0);
    k_agg1  <<<(NN + 7) / 8, 256>>>(b1, W2);
    k_agg2  <<<(NN + 63) / 64, 256>>>(out, b2);
}

// round 17
// speedup vs baseline: 1.3914x; 1.1210x over previous
#include <cuda_runtime.h>
#include <cuda_bf16.h>
#include <cuda_fp16.h>
#include <mma.h>

using namespace nvcuda;

#define NN    50000
#define DIN   128
#define HH    64
#define CC    2
#define EMAX  800000
#define NB    ((NN + 255) / 256)   // 196 scan blocks

// ---------------- scratch (static __device__, no allocation) ----------------
__device__ int d_flag64;
__device__ __align__(16) int     d_cnt[NN];
__device__ __align__(16) int     d_rp [NN + 1];
__device__ __align__(16) int     d_cur[NN];
__device__ __align__(16) int     d_bsum[NB];
__device__ __align__(16) int     d_col[EMAX];
__device__ __align__(16) float   d_dinv[NN];
__device__ __align__(16) __half2 d_g1h[(size_t)NN * 32];  // RAW x@W1 (fp16)
__device__ __align__(16) float   d_g2[NN * CC];           // layer-2 msgs (fp32)

__device__ __forceinline__ int edge_at(const void* p, long long i) {
    if (d_flag64) return (int)((const long long*)p)[i];
    return ((const int*)p)[i];
}

// ------------- init: zero counts; block 0 also probes int64/int32 -----------
__global__ void k_init(const int* __restrict__ p) {
    int i = blockIdx.x * blockDim.x + threadIdx.x;
    if (i < NN) d_cnt[i] = 0;
    if (blockIdx.x == 0) {
        __shared__ int ok;
        if (threadIdx.x == 0) ok = 1;
        __syncthreads();
        int bad = 0;
        for (int s = threadIdx.x; s < 1024; s += blockDim.x) {
            int lo = p[2 * s], hi = p[2 * s + 1];
            if (hi != 0 || lo < 0 || lo >= NN) bad = 1;
        }
        if (bad) atomicAnd(&ok, 0);
        __syncthreads();
        if (threadIdx.x == 0) d_flag64 = ok;
    }
}

// count in-degree (dst half only)
__global__ void k_count(const void* __restrict__ p, int E) {
    int i = blockIdx.x * blockDim.x + threadIdx.x;
    if (i >= E) return;
    int d = edge_at(p, (long long)E + i);
    atomicAdd(&d_cnt[d], 1);
}

// ---------------- scan stage 1: per-block scan + block sums ----------------
__global__ void __launch_bounds__(256) k_scan1() {
    __shared__ int sm[256];
    const int tid = threadIdx.x;
    const int i   = blockIdx.x * 256 + tid;
    int v = (i < NN) ? d_cnt[i] : 0;
    sm[tid] = v;
    __syncthreads();
    #pragma unroll
    for (int off = 1; off < 256; off <<= 1) {
        int t = (tid >= off) ? sm[tid - off] : 0;
        __syncthreads();
        sm[tid] += t;
        __syncthreads();
    }
    if (i < NN) d_rp[i] = sm[tid] - v;          // exclusive, block-local
    if (tid == 255) d_bsum[blockIdx.x] = sm[255];
}

// ---- scan stage 2 (merged): each block warp-sums its prefix of d_bsum ------
__global__ void __launch_bounds__(256) k_scan3() {
    __shared__ int soff;
    const int tid = threadIdx.x;
    const int b   = blockIdx.x;
    if (tid < 32) {
        int s = 0;
        for (int j = tid; j < b; j += 32) s += d_bsum[j];
        #pragma unroll
        for (int off = 16; off; off >>= 1)
            s += __shfl_down_sync(0xffffffff, s, off);
        if (tid == 0) soff = s;
    }
    __syncthreads();
    const int off = soff;
    const int i = b * 256 + tid;
    if (i < NN) {
        int r = d_rp[i] + off;
        d_rp[i]  = r;
        d_cur[i] = r;
        d_dinv[i] = rsqrtf((float)(1 + d_cnt[i]));
    }
    if (b == NB - 1 && tid == 0)
        d_rp[NN] = off + d_bsum[NB - 1];
}

// fill CSR col array (order nondeterministic; sum tolerance covers it)
__global__ void k_bucket(const void* __restrict__ p, int E) {
    int e = blockIdx.x * blockDim.x + threadIdx.x;
    if (e >= E) return;
    int s = edge_at(p, e);
    int d = edge_at(p, (long long)E + e);
    int pos = atomicAdd(&d_cur[d], 1);
    d_col[pos] = s;
}

// ---------------- layer 1 GEMM via tensor cores (fp16 in, fp32 acc) ---------
// tile: 64 nodes x 64 outs per block, 8 warps (2 M x 4 N), warp tile 32x16
// raw (unscaled) output -> fp16 messages; runs concurrent with preprocessing
#define XP 136   // xs pitch (halfs): 272B, 16B-multiple
#define WPH 72   // ws pitch (halfs): 144B, 16B-multiple
#define OP 68    // epilogue fp32 pitch: 272B
__global__ void __launch_bounds__(256) k_gemm1(const float* __restrict__ x,
                                               const float* __restrict__ W1) {
    __shared__ __align__(16) __half xs[64 * XP];    // 17408 B (aliased by epilogue)
    __shared__ __align__(16) __half ws[128 * WPH];  // 18432 B
    const int tid = threadIdx.x;
    const int nb  = blockIdx.x * 64;

    // stage x tile (64 rows x 128 cols fp32 -> fp16): 2048 float4, 8/thread
    for (int i = tid; i < 2048; i += 256) {
        int r = i >> 5, c4 = i & 31;
        int node = nb + r;
        float4 v = make_float4(0.f, 0.f, 0.f, 0.f);
        if (node < NN) v = ((const float4*)(x + (size_t)node * DIN))[c4];
        __half2* p = (__half2*)&xs[r * XP + 4 * c4];
        p[0] = __floats2half2_rn(v.x, v.y);
        p[1] = __floats2half2_rn(v.z, v.w);
    }
    // stage W1 (128 x 64 fp32 -> fp16): 2048 float4, 8/thread
    for (int i = tid; i < 2048; i += 256) {
        int r = i >> 4, c4 = i & 15;
        float4 v = ((const float4*)(W1 + (size_t)r * HH))[c4];
        __half2* p = (__half2*)&ws[r * WPH + 4 * c4];
        p[0] = __floats2half2_rn(v.x, v.y);
        p[1] = __floats2half2_rn(v.z, v.w);
    }
    __syncthreads();

    const int w      = tid >> 5;
    const int warp_m = w & 1;      // 0..1 : rows 32*warp_m
    const int warp_n = w >> 1;     // 0..3 : cols 16*warp_n

    wmma::fragment<wmma::accumulator, 16, 16, 16, float> fc[2];
    wmma::fill_fragment(fc[0], 0.0f);
    wmma::fill_fragment(fc[1], 0.0f);

    #pragma unroll
    for (int kk = 0; kk < DIN; kk += 16) {
        wmma::fragment<wmma::matrix_b, 16, 16, 16, __half, wmma::row_major> fb;
        wmma::load_matrix_sync(fb, &ws[kk * WPH + 16 * warp_n], WPH);
        #pragma unroll
        for (int i = 0; i < 2; i++) {
            wmma::fragment<wmma::matrix_a, 16, 16, 16, __half, wmma::row_major> fa;
            wmma::load_matrix_sync(fa, &xs[(32 * warp_m + 16 * i) * XP + kk], XP);
            wmma::mma_sync(fc[i], fa, fb, fc[i]);
        }
    }

    // epilogue: frags -> smem fp32 (aliases xs) -> fp16 global
    __syncthreads();
    float* outs = (float*)xs;   // 64 x OP fp32 = 17408 B, fits exactly
    #pragma unroll
    for (int i = 0; i < 2; i++)
        wmma::store_matrix_sync(&outs[(32 * warp_m + 16 * i) * OP + 16 * warp_n],
                                fc[i], OP, wmma::mem_row_major);
    __syncthreads();

    for (int e = tid; e < 64 * 32; e += 256) {   // one half2 per elem pair
        int r = e >> 5, c2 = e & 31;
        int node = nb + r;
        if (node < NN)
            d_g1h[(size_t)node * 32 + c2] =
                __floats2half2_rn(outs[r * OP + 2 * c2], outs[r * OP + 2 * c2 + 1]);
    }
}

// --- fused: aggregate layer1 (fp16 gather, dinv[s] per edge) + GEMM2 --------
// warp per node: lane holds cols [2*lane, 2*lane+1] as one __half2
__global__ void __launch_bounds__(256) k_agg1(const float* __restrict__ b1,
                                              const float* __restrict__ W2) {
    __shared__ float w2s[HH * CC];
    __shared__ float b1s[HH];
    const int tid = threadIdx.x;
    if (tid < HH * CC) w2s[tid] = W2[tid];
    if (tid < HH)      b1s[tid] = b1[tid];
    __syncthreads();

    const int warp = tid >> 5, lane = tid & 31;
    const int node = blockIdx.x * 8 + warp;
    if (node >= NN) return;

    const float di = d_dinv[node];
    float2 self = __half22float2(d_g1h[(size_t)node * 32 + lane]);
    float2 acc = make_float2(di * self.x, di * self.y);   // self-loop

    const int rs = d_rp[node], re = d_rp[node + 1];
    int k = rs;
    for (; k + 3 < re; k += 4) {
        int s0 = d_col[k], s1 = d_col[k + 1], s2 = d_col[k + 2], s3 = d_col[k + 3];
        float w0 = d_dinv[s0], w1 = d_dinv[s1], w2 = d_dinv[s2], w3 = d_dinv[s3];
        float2 v0 = __half22float2(d_g1h[(size_t)s0 * 32 + lane]);
        float2 v1 = __half22float2(d_g1h[(size_t)s1 * 32 + lane]);
        float2 v2 = __half22float2(d_g1h[(size_t)s2 * 32 + lane]);
        float2 v3 = __half22float2(d_g1h[(size_t)s3 * 32 + lane]);
        acc.x = fmaf(w0, v0.x, fmaf(w1, v1.x, fmaf(w2, v2.x, fmaf(w3, v3.x, acc.x))));
        acc.y = fmaf(w0, v0.y, fmaf(w1, v1.y, fmaf(w2, v2.y, fmaf(w3, v3.y, acc.y))));
    }
    for (; k < re; k++) {
        int s = d_col[k];
        float wgt = d_dinv[s];
        float2 v = __half22float2(d_g1h[(size_t)s * 32 + lane]);
        acc.x = fmaf(wgt, v.x, acc.x);
        acc.y = fmaf(wgt, v.y, acc.y);
    }

    float h0 = fmaxf(fmaf(di, acc.x, b1s[2 * lane    ]), 0.0f);
    float h1 = fmaxf(fmaf(di, acc.y, b1s[2 * lane + 1]), 0.0f);
    float a0 = h0 * w2s[4 * lane + 0] + h1 * w2s[4 * lane + 2];
    float a1 = h0 * w2s[4 * lane + 1] + h1 * w2s[4 * lane + 3];
    #pragma unroll
    for (int off = 16; off; off >>= 1) {
        a0 += __shfl_xor_sync(0xffffffff, a0, off);
        a1 += __shfl_xor_sync(0xffffffff, a1, off);
    }
    if (lane == 0)
        *(float2*)(d_g2 + node * CC) = make_float2(a0 * di, a1 * di);
}

// ---------- layer 2 aggregate: 4 lanes per node, quad shfl reduce -----------
__global__ void __launch_bounds__(256) k_agg2(float* __restrict__ out,
                                              const float* __restrict__ b2) {
    const int tid  = threadIdx.x;
    const int sub  = tid & 3;
    const int quad = tid >> 2;                  // 0..63 in block
    const int node = blockIdx.x * 64 + quad;
    if (node >= NN) return;
    const float2* __restrict__ g2v = (const float2*)d_g2;

    float2 acc = make_float2(0.0f, 0.0f);
    const int rs = d_rp[node], re = d_rp[node + 1];
    for (int k = rs + sub; k < re; k += 4) {
        float2 v = g2v[d_col[k]];
        acc.x += v.x; acc.y += v.y;
    }
    acc.x += __shfl_down_sync(0xffffffff, acc.x, 2, 4);
    acc.y += __shfl_down_sync(0xffffffff, acc.y, 2, 4);
    acc.x += __shfl_down_sync(0xffffffff, acc.x, 1, 4);
    acc.y += __shfl_down_sync(0xffffffff, acc.y, 1, 4);
    if (sub == 0) {
        float2 self = g2v[node];
        acc.x += self.x; acc.y += self.y;
        const float di = d_dinv[node];
        *(float2*)(out + node * CC) =
            make_float2(fmaf(di, acc.x, b2[0]), fmaf(di, acc.y, b2[1]));
    }
}

// ---------------- launch: fork gemm1 onto a side stream ---------------------
extern "C" void kernel_launch(void* const* d_in, const int* in_sizes, int n_in,
                              void* d_out, int out_size) {
    const float* x  = (const float*)d_in[0];
    const void*  ei = d_in[1];
    const float* W1 = (const float*)d_in[2];
    const float* b1 = (const float*)d_in[3];
    const float* W2 = (const float*)d_in[4];
    const float* b2 = (const float*)d_in[5];
    float* out = (float*)d_out;

    const int E = in_sizes[1] / 2;

    // created once, on the first (non-captured) correctness call
    static cudaStream_t s2 = nullptr;
    static cudaEvent_t evFork = nullptr, evJoin = nullptr;
    if (!s2) {
        cudaStreamCreateWithFlags(&s2, cudaStreamNonBlocking);
        cudaEventCreateWithFlags(&evFork, cudaEventDisableTiming);
        cudaEventCreateWithFlags(&evJoin, cudaEventDisableTiming);
    }

    // fork: gemm1 (independent of graph preprocessing) on side stream
    cudaEventRecord(evFork, 0);
    cudaStreamWaitEvent(s2, evFork, 0);
    k_gemm1<<<(NN + 63) / 64, 256, 0, s2>>>(x, W1);
    cudaEventRecord(evJoin, s2);

    // preprocessing chain on the main (captured) stream
    k_init  <<<NB, 256>>>((const int*)ei);
    k_count <<<(E + 255) / 256, 256>>>(ei, E);
    k_scan1 <<<NB, 256>>>();
    k_scan3 <<<NB, 256>>>();
    k_bucket<<<(E + 255) / 256, 256>>>(ei, E);

    // join, then aggregation
    cudaStreamWaitEvent(0, evJoin, 0);
    k_agg1  <<<(NN + 7) / 8, 256>>>(b1, W2);
    k_agg2  <<<(NN + 63) / 64, 256>>>(out, b2);
}